// round 11
// baseline (speedup 1.0000x reference)
#include <cuda_runtime.h>
#include <cuda_bf16.h>
#include <cuda_fp16.h>
#include <stdint.h>

// Problem constants
#define NR 4096
#define DIM 1024                 // bytes/row in fp8
#define NT 32                    // 128-row tiles per dim
#define NBLK 528                 // upper-tri 128x128 tiles
#define BKB 64                   // K bytes per stage
#define NSTG 16                  // 1024 / 64
#define STAGE_BYTES 16384        // A 128x64B + B 128x64B
#define SMEM_TOTAL (3 * STAGE_BYTES)   // 48KB static, 3-stage ring

// Scratch (static device globals; no runtime allocation)
__device__ uint8_t g_zq[NR * DIM];   // normalized z1 * 16, e4m3 (4 MB, L2-resident)
__device__ float g_pos[NR];
__device__ float g_negpart[NBLK];
__device__ unsigned g_ticket;        // last-CTA ticket (reset each run)

__device__ __forceinline__ uint32_t su32(const void* p) {
    return (uint32_t)__cvta_generic_to_shared(p);
}
__device__ __forceinline__ void cpasync16(uint32_t dst, const void* g) {
    asm volatile("cp.async.cg.shared.global [%0], [%1], 16;" :: "r"(dst), "l"(g));
}
#define CP_COMMIT() asm volatile("cp.async.commit_group;")
#define CP_WAIT(n)  asm volatile("cp.async.wait_group %0;" :: "n"(n))

#define LDMX4(R, addr) \
    asm volatile("ldmatrix.sync.aligned.m8n8.x4.shared.b16 {%0,%1,%2,%3}, [%4];" \
                 : "=r"((R)[0]), "=r"((R)[1]), "=r"((R)[2]), "=r"((R)[3]) : "r"(addr))

// fp8 MMA with f16 accumulator (2 packed regs)
__device__ __forceinline__ void mma16832h(uint32_t* c, const uint32_t* a, const uint32_t* b) {
    asm volatile(
        "mma.sync.aligned.m16n8k32.row.col.f16.e4m3.e4m3.f16 "
        "{%0,%1}, {%2,%3,%4,%5}, {%6,%7}, {%0,%1};"
        : "+r"(c[0]), "+r"(c[1])
        : "r"(a[0]), "r"(a[1]), "r"(a[2]), "r"(a[3]), "r"(b[0]), "r"(b[1]));
}

// packed 2^x for two halves — ONE MUFU op per two exponentials
__device__ __forceinline__ __half2 hexp2_x2(__half2 x) {
    __half2 r;
    asm("ex2.approx.f16x2 %0, %1;"
        : "=r"(*(uint32_t*)&r) : "r"(*(const uint32_t*)&x));
    return r;
}

__device__ __forceinline__ uint32_t pack4_e4m3(float v0, float v1, float v2, float v3) {
    uint16_t h01, h23;
    asm("cvt.rn.satfinite.e4m3x2.f32 %0, %1, %2;" : "=h"(h01) : "f"(v1), "f"(v0));
    asm("cvt.rn.satfinite.e4m3x2.f32 %0, %1, %2;" : "=h"(h23) : "f"(v3), "f"(v2));
    return (uint32_t)h01 | ((uint32_t)h23 << 16);
}

// SW64 swizzle for 64B-wide rows (conflict-free ldmatrix over 8 rows)
__device__ __forceinline__ uint32_t sw64(uint32_t off) {
    return off ^ ((off >> 3) & 0x30);
}

// -------------------------------------------------------------------------
// Kernel 1: half-row-per-warp normalize. 2048 blocks x 128 thr = 8192 warps
// (2x more than warp-per-row -> occupancy doubles). Emits e4m3 (z * 16).
// -------------------------------------------------------------------------
__global__ __launch_bounds__(128) void normalize_kernel(const float* __restrict__ z) {
    int warp = threadIdx.x >> 5, lane = threadIdx.x & 31;
    int rl = warp >> 1;              // row within block: 0..1
    int half = warp & 1;             // which 512-float half of the row
    int row = blockIdx.x * 2 + rl;

    const float4* z1p = (const float4*)(z + (size_t)row * DIM) + half * 128;
    const float4* z2p = (const float4*)(z + (size_t)(row + NR) * DIM) + half * 128;

    float4 a[4];
    float s1 = 0.f, s2 = 0.f, s12 = 0.f;
    #pragma unroll
    for (int i = 0; i < 4; i++) {
        a[i] = z1p[lane + 32 * i];
        float4 b = z2p[lane + 32 * i];
        s1  += a[i].x * a[i].x + a[i].y * a[i].y + a[i].z * a[i].z + a[i].w * a[i].w;
        s2  += b.x * b.x + b.y * b.y + b.z * b.z + b.w * b.w;
        s12 += a[i].x * b.x + a[i].y * b.y + a[i].z * b.z + a[i].w * b.w;
    }
    #pragma unroll
    for (int o = 16; o; o >>= 1) {
        s1  += __shfl_xor_sync(0xFFFFFFFFu, s1, o);
        s2  += __shfl_xor_sync(0xFFFFFFFFu, s2, o);
        s12 += __shfl_xor_sync(0xFFFFFFFFu, s12, o);
    }
    __shared__ float sh[2][2][3];
    if (lane == 0) {
        sh[rl][half][0] = s1; sh[rl][half][1] = s2; sh[rl][half][2] = s12;
    }
    __syncthreads();
    s1  = sh[rl][0][0] + sh[rl][1][0];
    s2  = sh[rl][0][1] + sh[rl][1][1];
    s12 = sh[rl][0][2] + sh[rl][1][2];

    float inv1 = 1.f / fmaxf(sqrtf(s1), 1e-12f);
    float q1 = 16.f * inv1;

    uint32_t* dst = (uint32_t*)(g_zq + (size_t)row * DIM) + half * 128;
    #pragma unroll
    for (int i = 0; i < 4; i++) {
        dst[lane + 32 * i] = pack4_e4m3(a[i].x * q1, a[i].y * q1, a[i].z * q1, a[i].w * q1);
    }
    if (half == 0 && lane == 0) {
        float inv2 = 1.f / fmaxf(sqrtf(s2), 1e-12f);
        float n1sq = s1 * inv1 * inv1;
        float n2sq = s2 * inv2 * inv2;
        float dp = n1sq + n2sq - 2.f * s12 * inv1 * inv2;
        g_pos[row] = logf(__expf(-0.5f * dp) + 1e-8f) + 1.f;
    }
}

// -------------------------------------------------------------------------
// Kernel 2: fp8 Gram (f16 acc) + f16x2 exp2 epilogue + fused last-CTA
// finalize. 528 CTAs x 256 thr, 2 CTAs/SM. CTA tile 128x128; warp 64x32.
// 16 K-stages of 64B; 3-stage static-smem ring (at the legacy-MMA floor).
// -------------------------------------------------------------------------
__global__ __launch_bounds__(256, 2) void gram_kernel(float* __restrict__ out) {
    __shared__ uint8_t dsm[SMEM_TOTAL];
    uint32_t smem_base = su32(dsm);
    int tid = threadIdx.x;
    int warp = tid >> 5, lane = tid & 31;
    int wr = warp >> 2, wc = warp & 3;   // warp grid 2 x 4 (rows x cols)

    // bid -> (ti, tj), tj >= ti
    int ti = 0, rem = blockIdx.x;
    #pragma unroll 1
    while (rem >= NT - ti) { rem -= NT - ti; ti++; }
    int tj = ti + rem;

    bool diag = (ti == tj);
    bool active = !(diag && (wc * 32 + 32 <= wr * 64));

    const uint8_t* Abase = g_zq + (size_t)ti * 128 * DIM;
    const uint8_t* Bbase = g_zq + (size_t)tj * 128 * DIM;

    uint32_t acc[4][4][2];   // f16x2 accumulators (= 256 * dot pairs)
    #pragma unroll
    for (int i = 0; i < 4; i++)
        #pragma unroll
        for (int j = 0; j < 4; j++) { acc[i][j][0] = 0u; acc[i][j][1] = 0u; }

    #define LOAD_STAGE(s, slot)                                                   \
        do {                                                                      \
            uint32_t base_ = smem_base + (slot) * STAGE_BYTES;                    \
            const uint8_t* Ak = Abase + (s) * BKB;                                \
            const uint8_t* Bk = Bbase + (s) * BKB;                                \
            _Pragma("unroll")                                                     \
            for (int x = tid; x < 512; x += 256) {                                \
                int r_ = x >> 2, c_ = x & 3;                                      \
                uint32_t off = sw64((uint32_t)(r_ * 64 + c_ * 16));               \
                cpasync16(base_ + off, Ak + (size_t)r_ * DIM + c_ * 16);          \
            }                                                                     \
            _Pragma("unroll")                                                     \
            for (int x = tid; x < 512; x += 256) {                                \
                int r_ = x >> 2, c_ = x & 3;                                      \
                uint32_t off = sw64((uint32_t)(r_ * 64 + c_ * 16));               \
                cpasync16(base_ + 8192 + off, Bk + (size_t)r_ * DIM + c_ * 16);   \
            }                                                                     \
            CP_COMMIT();                                                          \
        } while (0)

    LOAD_STAGE(0, 0);
    LOAD_STAGE(1, 1);
    LOAD_STAGE(2, 2);

    int slot = 0;
    #pragma unroll 1
    for (int s = 0; s < NSTG; s++) {
        if (s <= NSTG - 3)      CP_WAIT(2);
        else if (s == NSTG - 2) CP_WAIT(1);
        else                    CP_WAIT(0);
        __syncthreads();

        if (active) {
            uint32_t sa = smem_base + slot * STAGE_BYTES;
            uint32_t sb = sa + 8192;
            #pragma unroll
            for (int kk = 0; kk < 2; kk++) {
                uint32_t af[4][4];
                #pragma unroll
                for (int mi = 0; mi < 4; mi++) {
                    int r = wr * 64 + mi * 16 + (lane & 7) + ((lane >> 3) & 1) * 8;
                    int cb = kk * 32 + ((lane >> 4) & 1) * 16;
                    LDMX4(af[mi], sa + sw64((uint32_t)(r * 64 + cb)));
                }
                uint32_t bf[4][2];
                #pragma unroll
                for (int p = 0; p < 2; p++) {
                    int r = wc * 32 + p * 16 + ((lane >> 4) & 1) * 8 + (lane & 7);
                    int cb = kk * 32 + ((lane >> 3) & 1) * 16;
                    uint32_t t[4];
                    LDMX4(t, sb + sw64((uint32_t)(r * 64 + cb)));
                    bf[2 * p + 0][0] = t[0]; bf[2 * p + 0][1] = t[1];
                    bf[2 * p + 1][0] = t[2]; bf[2 * p + 1][1] = t[3];
                }
                #pragma unroll
                for (int mi = 0; mi < 4; mi++)
                    #pragma unroll
                    for (int ni = 0; ni < 4; ni++)
                        mma16832h(acc[mi][ni], af[mi], bf[ni]);
            }
        }

        if (s + 3 < NSTG) {
            __syncthreads();
            LOAD_STAGE(s + 3, slot);
        }
        slot = (slot == 2) ? 0 : slot + 1;
    }

    // ---- f16x2 epilogue: rows unit-norm -> g = exp(dot-1) = 2^(acc*k - log2e)
    const __half2 k2 = __float2half2_rn(1.44269504f / 256.f);
    const __half2 c2 = __float2half2_rn(-1.44269504f);
    __half2 hs0 = __float2half2_rn(0.f), hs1 = hs0, hs2 = hs0, hs3 = hs0;

    float local = 0.f;
    if (active) {
        if (!diag) {
            #pragma unroll
            for (int mi = 0; mi < 4; mi++)
                #pragma unroll
                for (int ni = 0; ni < 4; ni++) {
                    __half2 g0 = hexp2_x2(__hfma2(*(__half2*)&acc[mi][ni][0], k2, c2));
                    __half2 g1 = hexp2_x2(__hfma2(*(__half2*)&acc[mi][ni][1], k2, c2));
                    if (ni & 1) { hs1 = __hadd2(hs1, g0); hs3 = __hadd2(hs3, g1); }
                    else        { hs0 = __hadd2(hs0, g0); hs2 = __hadd2(hs2, g1); }
                }
        } else {
            int r0 = lane >> 2, c0 = (lane & 3) * 2;
            #pragma unroll
            for (int mi = 0; mi < 4; mi++) {
                int gi0 = wr * 64 + mi * 16 + r0;
                #pragma unroll
                for (int ni = 0; ni < 4; ni++) {
                    int gj0 = wc * 32 + ni * 8 + c0;
                    __half2 m0 = __floats2half2_rn(gj0 > gi0 ? 1.f : 0.f,
                                                   gj0 + 1 > gi0 ? 1.f : 0.f);
                    __half2 m1 = __floats2half2_rn(gj0 > gi0 + 8 ? 1.f : 0.f,
                                                   gj0 + 1 > gi0 + 8 ? 1.f : 0.f);
                    __half2 g0 = hexp2_x2(__hfma2(*(__half2*)&acc[mi][ni][0], k2, c2));
                    __half2 g1 = hexp2_x2(__hfma2(*(__half2*)&acc[mi][ni][1], k2, c2));
                    hs0 = __hfma2(g0, m0, hs0);
                    hs2 = __hfma2(g1, m1, hs2);
                }
            }
        }
        __half2 hs = __hadd2(__hadd2(hs0, hs1), __hadd2(hs2, hs3));
        local = 2.f * (__low2float(hs) + __high2float(hs));
    }

    #pragma unroll
    for (int o = 16; o; o >>= 1) local += __shfl_xor_sync(0xFFFFFFFFu, local, o);
    __shared__ float part[8];
    __shared__ unsigned s_last;
    if (lane == 0) part[warp] = local;
    __syncthreads();
    if (tid == 0) {
        float tot = 0.f;
        #pragma unroll
        for (int i = 0; i < 8; i++) tot += part[i];
        g_negpart[blockIdx.x] = tot;
        __threadfence();
        unsigned t = atomicAdd(&g_ticket, 1u);
        s_last = (t == NBLK - 1) ? 1u : 0u;
    }
    __syncthreads();

    // last CTA: deterministic finalize (replay-safe: resets ticket)
    if (s_last) {
        __threadfence();
        double* sh = (double*)dsm;
        double p = 0.0;
        for (int i = tid; i < NR; i += 256) p += (double)g_pos[i];
        sh[tid] = p;
        __syncthreads();
        for (int s = 128; s; s >>= 1) {
            if (tid < s) sh[tid] += sh[tid + s];
            __syncthreads();
        }
        double pos_sum = sh[0];
        __syncthreads();

        double n = 0.0;
        for (int i = tid; i < NBLK; i += 256) n += (double)g_negpart[i];
        sh[tid] = n;
        __syncthreads();
        for (int s = 128; s; s >>= 1) {
            if (tid < s) sh[tid] += sh[tid + s];
            __syncthreads();
        }
        if (tid == 0) {
            double star_mean = sh[0] / ((double)NR * (double)(NR - 1)) + 1e-8;
            out[0] = (float)(-(pos_sum / (double)NR) + 64.0 * star_mean);
            g_ticket = 0;
            __threadfence();
        }
    }
}

extern "C" void kernel_launch(void* const* d_in, const int* in_sizes, int n_in,
                              void* d_out, int out_size) {
    const float* z = (const float*)d_in[0];
    float* out = (float*)d_out;
    normalize_kernel<<<2048, 128>>>(z);
    gram_kernel<<<NBLK, 256>>>(out);
}

// round 12
// speedup vs baseline: 1.0561x; 1.0561x over previous
#include <cuda_runtime.h>
#include <cuda_bf16.h>
#include <cuda_fp16.h>
#include <stdint.h>

// Problem constants
#define NR 4096
#define DIM 1024                 // bytes/row in fp8
#define NT 32                    // 128-row tiles per dim
#define NBLK 528                 // upper-tri 128x128 tiles
#define BKB 64                   // K bytes per stage
#define NSTG 16                  // 1024 / 64
#define STAGE_BYTES 16384        // A 128x64B + B 128x64B
#define SMEM_TOTAL (3 * STAGE_BYTES)   // 48KB static, 3-stage ring

// Scratch (static device globals; no runtime allocation)
__device__ uint8_t g_zq[NR * DIM];   // normalized z1 * 16, e4m3 (4 MB, L2-resident)
__device__ float g_pos[NR];
__device__ float g_negpart[NBLK];

__device__ __forceinline__ uint32_t su32(const void* p) {
    return (uint32_t)__cvta_generic_to_shared(p);
}
__device__ __forceinline__ void cpasync16(uint32_t dst, const void* g) {
    asm volatile("cp.async.cg.shared.global [%0], [%1], 16;" :: "r"(dst), "l"(g));
}
#define CP_COMMIT() asm volatile("cp.async.commit_group;")
#define CP_WAIT(n)  asm volatile("cp.async.wait_group %0;" :: "n"(n))

#define LDMX4(R, addr) \
    asm volatile("ldmatrix.sync.aligned.m8n8.x4.shared.b16 {%0,%1,%2,%3}, [%4];" \
                 : "=r"((R)[0]), "=r"((R)[1]), "=r"((R)[2]), "=r"((R)[3]) : "r"(addr))

// fp8 MMA with f16 accumulator (2 packed regs)
__device__ __forceinline__ void mma16832h(uint32_t* c, const uint32_t* a, const uint32_t* b) {
    asm volatile(
        "mma.sync.aligned.m16n8k32.row.col.f16.e4m3.e4m3.f16 "
        "{%0,%1}, {%2,%3,%4,%5}, {%6,%7}, {%0,%1};"
        : "+r"(c[0]), "+r"(c[1])
        : "r"(a[0]), "r"(a[1]), "r"(a[2]), "r"(a[3]), "r"(b[0]), "r"(b[1]));
}

// packed 2^x for two halves — ONE MUFU op per two exponentials
__device__ __forceinline__ __half2 hexp2_x2(__half2 x) {
    __half2 r;
    asm("ex2.approx.f16x2 %0, %1;"
        : "=r"(*(uint32_t*)&r) : "r"(*(const uint32_t*)&x));
    return r;
}

__device__ __forceinline__ uint32_t pack4_e4m3(float v0, float v1, float v2, float v3) {
    uint16_t h01, h23;
    asm("cvt.rn.satfinite.e4m3x2.f32 %0, %1, %2;" : "=h"(h01) : "f"(v1), "f"(v0));
    asm("cvt.rn.satfinite.e4m3x2.f32 %0, %1, %2;" : "=h"(h23) : "f"(v3), "f"(v2));
    return (uint32_t)h01 | ((uint32_t)h23 << 16);
}

// SW64 swizzle for 64B-wide rows (conflict-free ldmatrix over 8 rows)
__device__ __forceinline__ uint32_t sw64(uint32_t off) {
    return off ^ ((off >> 3) & 0x30);
}

// -------------------------------------------------------------------------
// Kernel 1: half-row-per-warp normalize. 2048 blocks x 128 thr = 8192 warps
// (2x occupancy vs warp-per-row). Emits e4m3 (z * 16).
// -------------------------------------------------------------------------
__global__ __launch_bounds__(128) void normalize_kernel(const float* __restrict__ z) {
    int warp = threadIdx.x >> 5, lane = threadIdx.x & 31;
    int rl = warp >> 1;              // row within block: 0..1
    int half = warp & 1;             // which 512-float half of the row
    int row = blockIdx.x * 2 + rl;

    const float4* z1p = (const float4*)(z + (size_t)row * DIM) + half * 128;
    const float4* z2p = (const float4*)(z + (size_t)(row + NR) * DIM) + half * 128;

    float4 a[4];
    float s1 = 0.f, s2 = 0.f, s12 = 0.f;
    #pragma unroll
    for (int i = 0; i < 4; i++) {
        a[i] = z1p[lane + 32 * i];
        float4 b = z2p[lane + 32 * i];
        s1  += a[i].x * a[i].x + a[i].y * a[i].y + a[i].z * a[i].z + a[i].w * a[i].w;
        s2  += b.x * b.x + b.y * b.y + b.z * b.z + b.w * b.w;
        s12 += a[i].x * b.x + a[i].y * b.y + a[i].z * b.z + a[i].w * b.w;
    }
    #pragma unroll
    for (int o = 16; o; o >>= 1) {
        s1  += __shfl_xor_sync(0xFFFFFFFFu, s1, o);
        s2  += __shfl_xor_sync(0xFFFFFFFFu, s2, o);
        s12 += __shfl_xor_sync(0xFFFFFFFFu, s12, o);
    }
    __shared__ float sh[2][2][3];
    if (lane == 0) {
        sh[rl][half][0] = s1; sh[rl][half][1] = s2; sh[rl][half][2] = s12;
    }
    __syncthreads();
    s1  = sh[rl][0][0] + sh[rl][1][0];
    s2  = sh[rl][0][1] + sh[rl][1][1];
    s12 = sh[rl][0][2] + sh[rl][1][2];

    float inv1 = 1.f / fmaxf(sqrtf(s1), 1e-12f);
    float q1 = 16.f * inv1;

    uint32_t* dst = (uint32_t*)(g_zq + (size_t)row * DIM) + half * 128;
    #pragma unroll
    for (int i = 0; i < 4; i++) {
        dst[lane + 32 * i] = pack4_e4m3(a[i].x * q1, a[i].y * q1, a[i].z * q1, a[i].w * q1);
    }
    if (half == 0 && lane == 0) {
        float inv2 = 1.f / fmaxf(sqrtf(s2), 1e-12f);
        float n1sq = s1 * inv1 * inv1;
        float n2sq = s2 * inv2 * inv2;
        float dp = n1sq + n2sq - 2.f * s12 * inv1 * inv2;
        g_pos[row] = logf(__expf(-0.5f * dp) + 1e-8f) + 1.f;
    }
}

// -------------------------------------------------------------------------
// Kernel 2: fp8 Gram (f16 acc) + f16x2 exp2 epilogue (exact R10 config —
// best measured, at the legacy-MMA issue floor).
// 528 CTAs x 256 thr, 2 CTAs/SM. CTA tile 128x128; warp tile 64x32.
// 16 K-stages of 64B; 3-stage static-smem ring.
// -------------------------------------------------------------------------
__global__ __launch_bounds__(256, 2) void gram_kernel() {
    __shared__ uint8_t dsm[SMEM_TOTAL];
    uint32_t smem_base = su32(dsm);
    int tid = threadIdx.x;
    int warp = tid >> 5, lane = tid & 31;
    int wr = warp >> 2, wc = warp & 3;   // warp grid 2 x 4 (rows x cols)

    // bid -> (ti, tj), tj >= ti
    int ti = 0, rem = blockIdx.x;
    #pragma unroll 1
    while (rem >= NT - ti) { rem -= NT - ti; ti++; }
    int tj = ti + rem;

    bool diag = (ti == tj);
    bool active = !(diag && (wc * 32 + 32 <= wr * 64));

    const uint8_t* Abase = g_zq + (size_t)ti * 128 * DIM;
    const uint8_t* Bbase = g_zq + (size_t)tj * 128 * DIM;

    uint32_t acc[4][4][2];   // f16x2 accumulators (= 256 * dot pairs)
    #pragma unroll
    for (int i = 0; i < 4; i++)
        #pragma unroll
        for (int j = 0; j < 4; j++) { acc[i][j][0] = 0u; acc[i][j][1] = 0u; }

    #define LOAD_STAGE(s, slot)                                                   \
        do {                                                                      \
            uint32_t base_ = smem_base + (slot) * STAGE_BYTES;                    \
            const uint8_t* Ak = Abase + (s) * BKB;                                \
            const uint8_t* Bk = Bbase + (s) * BKB;                                \
            _Pragma("unroll")                                                     \
            for (int x = tid; x < 512; x += 256) {                                \
                int r_ = x >> 2, c_ = x & 3;                                      \
                uint32_t off = sw64((uint32_t)(r_ * 64 + c_ * 16));               \
                cpasync16(base_ + off, Ak + (size_t)r_ * DIM + c_ * 16);          \
            }                                                                     \
            _Pragma("unroll")                                                     \
            for (int x = tid; x < 512; x += 256) {                                \
                int r_ = x >> 2, c_ = x & 3;                                      \
                uint32_t off = sw64((uint32_t)(r_ * 64 + c_ * 16));               \
                cpasync16(base_ + 8192 + off, Bk + (size_t)r_ * DIM + c_ * 16);   \
            }                                                                     \
            CP_COMMIT();                                                          \
        } while (0)

    LOAD_STAGE(0, 0);
    LOAD_STAGE(1, 1);
    LOAD_STAGE(2, 2);

    int slot = 0;
    #pragma unroll 1
    for (int s = 0; s < NSTG; s++) {
        if (s <= NSTG - 3)      CP_WAIT(2);
        else if (s == NSTG - 2) CP_WAIT(1);
        else                    CP_WAIT(0);
        __syncthreads();

        if (active) {
            uint32_t sa = smem_base + slot * STAGE_BYTES;
            uint32_t sb = sa + 8192;
            #pragma unroll
            for (int kk = 0; kk < 2; kk++) {
                uint32_t af[4][4];
                #pragma unroll
                for (int mi = 0; mi < 4; mi++) {
                    int r = wr * 64 + mi * 16 + (lane & 7) + ((lane >> 3) & 1) * 8;
                    int cb = kk * 32 + ((lane >> 4) & 1) * 16;
                    LDMX4(af[mi], sa + sw64((uint32_t)(r * 64 + cb)));
                }
                uint32_t bf[4][2];
                #pragma unroll
                for (int p = 0; p < 2; p++) {
                    int r = wc * 32 + p * 16 + ((lane >> 4) & 1) * 8 + (lane & 7);
                    int cb = kk * 32 + ((lane >> 3) & 1) * 16;
                    uint32_t t[4];
                    LDMX4(t, sb + sw64((uint32_t)(r * 64 + cb)));
                    bf[2 * p + 0][0] = t[0]; bf[2 * p + 0][1] = t[1];
                    bf[2 * p + 1][0] = t[2]; bf[2 * p + 1][1] = t[3];
                }
                #pragma unroll
                for (int mi = 0; mi < 4; mi++)
                    #pragma unroll
                    for (int ni = 0; ni < 4; ni++)
                        mma16832h(acc[mi][ni], af[mi], bf[ni]);
            }
        }

        if (s + 3 < NSTG) {
            __syncthreads();
            LOAD_STAGE(s + 3, slot);
        }
        slot = (slot == 2) ? 0 : slot + 1;
    }

    // ---- f16x2 epilogue: rows unit-norm -> g = exp(dot-1) = 2^(acc*k - log2e)
    const __half2 k2 = __float2half2_rn(1.44269504f / 256.f);
    const __half2 c2 = __float2half2_rn(-1.44269504f);
    __half2 hs0 = __float2half2_rn(0.f), hs1 = hs0, hs2 = hs0, hs3 = hs0;

    float local = 0.f;
    if (active) {
        if (!diag) {
            #pragma unroll
            for (int mi = 0; mi < 4; mi++)
                #pragma unroll
                for (int ni = 0; ni < 4; ni++) {
                    __half2 g0 = hexp2_x2(__hfma2(*(__half2*)&acc[mi][ni][0], k2, c2));
                    __half2 g1 = hexp2_x2(__hfma2(*(__half2*)&acc[mi][ni][1], k2, c2));
                    if (ni & 1) { hs1 = __hadd2(hs1, g0); hs3 = __hadd2(hs3, g1); }
                    else        { hs0 = __hadd2(hs0, g0); hs2 = __hadd2(hs2, g1); }
                }
        } else {
            int r0 = lane >> 2, c0 = (lane & 3) * 2;
            #pragma unroll
            for (int mi = 0; mi < 4; mi++) {
                int gi0 = wr * 64 + mi * 16 + r0;
                #pragma unroll
                for (int ni = 0; ni < 4; ni++) {
                    int gj0 = wc * 32 + ni * 8 + c0;
                    __half2 m0 = __floats2half2_rn(gj0 > gi0 ? 1.f : 0.f,
                                                   gj0 + 1 > gi0 ? 1.f : 0.f);
                    __half2 m1 = __floats2half2_rn(gj0 > gi0 + 8 ? 1.f : 0.f,
                                                   gj0 + 1 > gi0 + 8 ? 1.f : 0.f);
                    __half2 g0 = hexp2_x2(__hfma2(*(__half2*)&acc[mi][ni][0], k2, c2));
                    __half2 g1 = hexp2_x2(__hfma2(*(__half2*)&acc[mi][ni][1], k2, c2));
                    hs0 = __hfma2(g0, m0, hs0);
                    hs2 = __hfma2(g1, m1, hs2);
                }
            }
        }
        __half2 hs = __hadd2(__hadd2(hs0, hs1), __hadd2(hs2, hs3));
        local = 2.f * (__low2float(hs) + __high2float(hs));
    }

    #pragma unroll
    for (int o = 16; o; o >>= 1) local += __shfl_xor_sync(0xFFFFFFFFu, local, o);
    __shared__ float part[8];
    if (lane == 0) part[warp] = local;
    __syncthreads();
    if (tid == 0) {
        float tot = 0.f;
        #pragma unroll
        for (int i = 0; i < 8; i++) tot += part[i];
        g_negpart[blockIdx.x] = tot;
    }
}

// -------------------------------------------------------------------------
// Kernel 3: deterministic finalize
// -------------------------------------------------------------------------
__global__ __launch_bounds__(256) void finalize_kernel(float* out) {
    __shared__ double sh[256];
    int tid = threadIdx.x;

    double p = 0.0;
    for (int i = tid; i < NR; i += 256) p += (double)g_pos[i];
    sh[tid] = p;
    __syncthreads();
    for (int s = 128; s; s >>= 1) {
        if (tid < s) sh[tid] += sh[tid + s];
        __syncthreads();
    }
    double pos_sum = sh[0];
    __syncthreads();

    double n = 0.0;
    for (int i = tid; i < NBLK; i += 256) n += (double)g_negpart[i];
    sh[tid] = n;
    __syncthreads();
    for (int s = 128; s; s >>= 1) {
        if (tid < s) sh[tid] += sh[tid + s];
        __syncthreads();
    }
    if (tid == 0) {
        double star_mean = sh[0] / ((double)NR * (double)(NR - 1)) + 1e-8;
        double loss = -(pos_sum / (double)NR) + 64.0 * star_mean;
        out[0] = (float)loss;
    }
}

extern "C" void kernel_launch(void* const* d_in, const int* in_sizes, int n_in,
                              void* d_out, int out_size) {
    const float* z = (const float*)d_in[0];
    float* out = (float*)d_out;
    normalize_kernel<<<2048, 128>>>(z);
    gram_kernel<<<NBLK, 256>>>();
    finalize_kernel<<<1, 256>>>(out);
}

// round 13
// speedup vs baseline: 1.0608x; 1.0044x over previous
#include <cuda_runtime.h>
#include <cuda_bf16.h>
#include <cuda_fp16.h>
#include <stdint.h>

// Problem constants
#define NR 4096
#define DIM 1024                 // bytes/row in fp8
#define NT 32                    // 128-row tiles per dim
#define NBLK 528                 // upper-tri 128x128 tiles
#define BKB 64                   // K bytes per stage
#define NSTG 16                  // 1024 / 64
#define STAGE_BYTES 16384        // A 128x64B + B 128x64B
#define SMEM_TOTAL (3 * STAGE_BYTES)   // 48KB static, 3-stage ring

// Scratch (static device globals; no runtime allocation)
__device__ uint8_t g_zq[NR * DIM];   // normalized z1 * 16, e4m3 (4 MB, L2-resident)
__device__ float g_pos[NR];
__device__ float g_negpart[NBLK];

__device__ __forceinline__ uint32_t su32(const void* p) {
    return (uint32_t)__cvta_generic_to_shared(p);
}
__device__ __forceinline__ void cpasync16(uint32_t dst, const void* g) {
    asm volatile("cp.async.cg.shared.global [%0], [%1], 16;" :: "r"(dst), "l"(g));
}
#define CP_COMMIT() asm volatile("cp.async.commit_group;")
#define CP_WAIT(n)  asm volatile("cp.async.wait_group %0;" :: "n"(n))

#define LDMX4(R, addr) \
    asm volatile("ldmatrix.sync.aligned.m8n8.x4.shared.b16 {%0,%1,%2,%3}, [%4];" \
                 : "=r"((R)[0]), "=r"((R)[1]), "=r"((R)[2]), "=r"((R)[3]) : "r"(addr))

// fp8 MMA with f16 accumulator (2 packed regs)
__device__ __forceinline__ void mma16832h(uint32_t* c, const uint32_t* a, const uint32_t* b) {
    asm volatile(
        "mma.sync.aligned.m16n8k32.row.col.f16.e4m3.e4m3.f16 "
        "{%0,%1}, {%2,%3,%4,%5}, {%6,%7}, {%0,%1};"
        : "+r"(c[0]), "+r"(c[1])
        : "r"(a[0]), "r"(a[1]), "r"(a[2]), "r"(a[3]), "r"(b[0]), "r"(b[1]));
}

// packed 2^x for two halves — ONE MUFU op per two exponentials
__device__ __forceinline__ __half2 hexp2_x2(__half2 x) {
    __half2 r;
    asm("ex2.approx.f16x2 %0, %1;"
        : "=r"(*(uint32_t*)&r) : "r"(*(const uint32_t*)&x));
    return r;
}

__device__ __forceinline__ uint32_t pack4_e4m3(float v0, float v1, float v2, float v3) {
    uint16_t h01, h23;
    asm("cvt.rn.satfinite.e4m3x2.f32 %0, %1, %2;" : "=h"(h01) : "f"(v1), "f"(v0));
    asm("cvt.rn.satfinite.e4m3x2.f32 %0, %1, %2;" : "=h"(h23) : "f"(v3), "f"(v2));
    return (uint32_t)h01 | ((uint32_t)h23 << 16);
}

// SW64 swizzle for 64B-wide rows (conflict-free ldmatrix over 8 rows)
__device__ __forceinline__ uint32_t sw64(uint32_t off) {
    return off ^ ((off >> 3) & 0x30);
}

// -------------------------------------------------------------------------
// Kernel 1: warp-per-row-pair normalize (best measured: 9.3us, R10 exact).
// -------------------------------------------------------------------------
__global__ __launch_bounds__(128) void normalize_kernel(const float* __restrict__ z) {
    int warp = threadIdx.x >> 5, lane = threadIdx.x & 31;
    int row = blockIdx.x * 4 + warp;

    const float4* z1p = (const float4*)(z + (size_t)row * DIM);
    const float4* z2p = (const float4*)(z + (size_t)(row + NR) * DIM);

    float4 a[8];
    float s1 = 0.f, s2 = 0.f, s12 = 0.f;
    #pragma unroll
    for (int i = 0; i < 8; i++) {
        a[i] = z1p[lane + 32 * i];
        float4 b = z2p[lane + 32 * i];
        s1  += a[i].x * a[i].x + a[i].y * a[i].y + a[i].z * a[i].z + a[i].w * a[i].w;
        s2  += b.x * b.x + b.y * b.y + b.z * b.z + b.w * b.w;
        s12 += a[i].x * b.x + a[i].y * b.y + a[i].z * b.z + a[i].w * b.w;
    }
    #pragma unroll
    for (int o = 16; o; o >>= 1) {
        s1  += __shfl_xor_sync(0xFFFFFFFFu, s1, o);
        s2  += __shfl_xor_sync(0xFFFFFFFFu, s2, o);
        s12 += __shfl_xor_sync(0xFFFFFFFFu, s12, o);
    }
    float inv1 = 1.f / fmaxf(sqrtf(s1), 1e-12f);
    float inv2 = 1.f / fmaxf(sqrtf(s2), 1e-12f);
    float q1 = 16.f * inv1;

    uint32_t* dst = (uint32_t*)(g_zq + (size_t)row * DIM);
    #pragma unroll
    for (int i = 0; i < 8; i++) {
        dst[lane + 32 * i] = pack4_e4m3(a[i].x * q1, a[i].y * q1, a[i].z * q1, a[i].w * q1);
    }
    if (lane == 0) {
        float n1sq = s1 * inv1 * inv1;
        float n2sq = s2 * inv2 * inv2;
        float dp = n1sq + n2sq - 2.f * s12 * inv1 * inv2;
        g_pos[row] = logf(__expf(-0.5f * dp) + 1e-8f) + 1.f;
    }
}

// -------------------------------------------------------------------------
// Kernel 2: fp8 Gram (f16 acc) + f16x2 exp2 epilogue. R10 config with ALL
// mainloop address math hoisted (LDSM offsets + load pointers invariant).
// 528 CTAs x 256 thr, 2 CTAs/SM. CTA tile 128x128; warp tile 64x32.
// 16 K-stages of 64B; 3-stage static-smem ring.
// -------------------------------------------------------------------------
__global__ __launch_bounds__(256, 2) void gram_kernel() {
    __shared__ uint8_t dsm[SMEM_TOTAL];
    uint32_t smem_base = su32(dsm);
    int tid = threadIdx.x;
    int warp = tid >> 5, lane = tid & 31;
    int wr = warp >> 2, wc = warp & 3;   // warp grid 2 x 4 (rows x cols)

    // bid -> (ti, tj), tj >= ti
    int ti = 0, rem = blockIdx.x;
    #pragma unroll 1
    while (rem >= NT - ti) { rem -= NT - ti; ti++; }
    int tj = ti + rem;

    bool diag = (ti == tj);
    bool active = !(diag && (wc * 32 + 32 <= wr * 64));

    // ---- hoisted per-thread cp.async state (stage-invariant smem offsets,
    //      incrementally-advanced global pointers) ----
    int lr = tid >> 2, lc = tid & 3;
    uint32_t ldoff = sw64((uint32_t)(lr * 64 + lc * 16));
    const uint8_t* gA0 = g_zq + (size_t)ti * 128 * DIM + (size_t)lr * DIM + lc * 16;
    const uint8_t* gA1 = gA0 + 64 * DIM;                 // rows 64..127 (x=tid+256)
    const uint8_t* gB0 = g_zq + (size_t)tj * 128 * DIM + (size_t)lr * DIM + lc * 16;
    const uint8_t* gB1 = gB0 + 64 * DIM;
    uint32_t ldoff1 = sw64((uint32_t)((lr + 64) * 64 + lc * 16));

    // ---- hoisted per-warp LDSM swizzled offsets (relative to slot base) ----
    uint32_t aoff[2][4], boff[2][2];
    {
        int ra = wr * 64 + (lane & 7) + ((lane >> 3) & 1) * 8;
        int rb = wc * 32 + ((lane >> 4) & 1) * 8 + (lane & 7);
        #pragma unroll
        for (int kk = 0; kk < 2; kk++) {
            int ca = kk * 32 + ((lane >> 4) & 1) * 16;
            int cb = kk * 32 + ((lane >> 3) & 1) * 16;
            #pragma unroll
            for (int mi = 0; mi < 4; mi++)
                aoff[kk][mi] = sw64((uint32_t)((ra + mi * 16) * 64 + ca));
            #pragma unroll
            for (int p = 0; p < 2; p++)
                boff[kk][p] = 8192 + sw64((uint32_t)((rb + p * 16) * 64 + cb));
        }
    }

    uint32_t acc[4][4][2];   // f16x2 accumulators (= 256 * dot pairs)
    #pragma unroll
    for (int i = 0; i < 4; i++)
        #pragma unroll
        for (int j = 0; j < 4; j++) { acc[i][j][0] = 0u; acc[i][j][1] = 0u; }

    #define LOAD_STAGE(slot)                                                      \
        do {                                                                      \
            uint32_t base_ = smem_base + (slot) * STAGE_BYTES;                    \
            cpasync16(base_ + ldoff,         gA0);                                \
            cpasync16(base_ + ldoff1,        gA1);                                \
            cpasync16(base_ + 8192 + ldoff,  gB0);                                \
            cpasync16(base_ + 8192 + ldoff1, gB1);                                \
            gA0 += BKB; gA1 += BKB; gB0 += BKB; gB1 += BKB;                       \
            CP_COMMIT();                                                          \
        } while (0)

    LOAD_STAGE(0);
    LOAD_STAGE(1);
    LOAD_STAGE(2);

    int slot = 0;
    #pragma unroll 1
    for (int s = 0; s < NSTG; s++) {
        if (s <= NSTG - 3)      CP_WAIT(2);
        else if (s == NSTG - 2) CP_WAIT(1);
        else                    CP_WAIT(0);
        __syncthreads();

        if (active) {
            uint32_t sa = smem_base + slot * STAGE_BYTES;
            #pragma unroll
            for (int kk = 0; kk < 2; kk++) {
                uint32_t af[4][4];
                #pragma unroll
                for (int mi = 0; mi < 4; mi++)
                    LDMX4(af[mi], sa + aoff[kk][mi]);
                uint32_t bf[4][2];
                #pragma unroll
                for (int p = 0; p < 2; p++) {
                    uint32_t t[4];
                    LDMX4(t, sa + boff[kk][p]);
                    bf[2 * p + 0][0] = t[0]; bf[2 * p + 0][1] = t[1];
                    bf[2 * p + 1][0] = t[2]; bf[2 * p + 1][1] = t[3];
                }
                #pragma unroll
                for (int mi = 0; mi < 4; mi++)
                    #pragma unroll
                    for (int ni = 0; ni < 4; ni++)
                        mma16832h(acc[mi][ni], af[mi], bf[ni]);
            }
        }

        if (s + 3 < NSTG) {
            __syncthreads();
            LOAD_STAGE(slot);
        }
        slot = (slot == 2) ? 0 : slot + 1;
    }

    // ---- f16x2 epilogue: rows unit-norm -> g = exp(dot-1) = 2^(acc*k - log2e)
    const __half2 k2 = __float2half2_rn(1.44269504f / 256.f);
    const __half2 c2 = __float2half2_rn(-1.44269504f);
    __half2 hs0 = __float2half2_rn(0.f), hs1 = hs0, hs2 = hs0, hs3 = hs0;

    float local = 0.f;
    if (active) {
        if (!diag) {
            #pragma unroll
            for (int mi = 0; mi < 4; mi++)
                #pragma unroll
                for (int ni = 0; ni < 4; ni++) {
                    __half2 g0 = hexp2_x2(__hfma2(*(__half2*)&acc[mi][ni][0], k2, c2));
                    __half2 g1 = hexp2_x2(__hfma2(*(__half2*)&acc[mi][ni][1], k2, c2));
                    if (ni & 1) { hs1 = __hadd2(hs1, g0); hs3 = __hadd2(hs3, g1); }
                    else        { hs0 = __hadd2(hs0, g0); hs2 = __hadd2(hs2, g1); }
                }
        } else {
            int r0 = lane >> 2, c0 = (lane & 3) * 2;
            #pragma unroll
            for (int mi = 0; mi < 4; mi++) {
                int gi0 = wr * 64 + mi * 16 + r0;
                #pragma unroll
                for (int ni = 0; ni < 4; ni++) {
                    int gj0 = wc * 32 + ni * 8 + c0;
                    __half2 m0 = __floats2half2_rn(gj0 > gi0 ? 1.f : 0.f,
                                                   gj0 + 1 > gi0 ? 1.f : 0.f);
                    __half2 m1 = __floats2half2_rn(gj0 > gi0 + 8 ? 1.f : 0.f,
                                                   gj0 + 1 > gi0 + 8 ? 1.f : 0.f);
                    __half2 g0 = hexp2_x2(__hfma2(*(__half2*)&acc[mi][ni][0], k2, c2));
                    __half2 g1 = hexp2_x2(__hfma2(*(__half2*)&acc[mi][ni][1], k2, c2));
                    hs0 = __hfma2(g0, m0, hs0);
                    hs2 = __hfma2(g1, m1, hs2);
                }
            }
        }
        __half2 hs = __hadd2(__hadd2(hs0, hs1), __hadd2(hs2, hs3));
        local = 2.f * (__low2float(hs) + __high2float(hs));
    }

    #pragma unroll
    for (int o = 16; o; o >>= 1) local += __shfl_xor_sync(0xFFFFFFFFu, local, o);
    __shared__ float part[8];
    if (lane == 0) part[warp] = local;
    __syncthreads();
    if (tid == 0) {
        float tot = 0.f;
        #pragma unroll
        for (int i = 0; i < 8; i++) tot += part[i];
        g_negpart[blockIdx.x] = tot;
    }
}

// -------------------------------------------------------------------------
// Kernel 3: deterministic finalize
// -------------------------------------------------------------------------
__global__ __launch_bounds__(256) void finalize_kernel(float* out) {
    __shared__ double sh[256];
    int tid = threadIdx.x;

    double p = 0.0;
    for (int i = tid; i < NR; i += 256) p += (double)g_pos[i];
    sh[tid] = p;
    __syncthreads();
    for (int s = 128; s; s >>= 1) {
        if (tid < s) sh[tid] += sh[tid + s];
        __syncthreads();
    }
    double pos_sum = sh[0];
    __syncthreads();

    double n = 0.0;
    for (int i = tid; i < NBLK; i += 256) n += (double)g_negpart[i];
    sh[tid] = n;
    __syncthreads();
    for (int s = 128; s; s >>= 1) {
        if (tid < s) sh[tid] += sh[tid + s];
        __syncthreads();
    }
    if (tid == 0) {
        double star_mean = sh[0] / ((double)NR * (double)(NR - 1)) + 1e-8;
        double loss = -(pos_sum / (double)NR) + 64.0 * star_mean;
        out[0] = (float)loss;
    }
}

extern "C" void kernel_launch(void* const* d_in, const int* in_sizes, int n_in,
                              void* d_out, int out_size) {
    const float* z = (const float*)d_in[0];
    float* out = (float*)d_out;
    normalize_kernel<<<1024, 128>>>(z);
    gram_kernel<<<NBLK, 256>>>();
    finalize_kernel<<<1, 256>>>(out);
}

// round 14
// speedup vs baseline: 1.1236x; 1.0592x over previous
#include <cuda_runtime.h>
#include <cuda_bf16.h>
#include <cuda_fp16.h>
#include <stdint.h>

// Problem constants
#define NR 4096
#define DIM 1024                 // bytes/row in fp8
#define NT 32                    // 128-row tiles per dim
#define NOFF 496                 // off-diagonal tiles (ti < tj)
#define NBLK 528                 // 496 off-diag + 32 diag (diag scheduled LAST)
#define BKB 64                   // K bytes per stage
#define NSTG 16                  // 1024 / 64
#define STAGE_BYTES 16384        // A 128x64B + B 128x64B
#define SMEM_TOTAL (3 * STAGE_BYTES)   // 48KB static, 3-stage ring

// Scratch (static device globals; no runtime allocation)
__device__ uint8_t g_zq[NR * DIM];   // normalized z1 * 16, e4m3 (4 MB, L2-resident)
__device__ float g_pos[NR];
__device__ float g_negpart[NBLK];

__device__ __forceinline__ uint32_t su32(const void* p) {
    return (uint32_t)__cvta_generic_to_shared(p);
}
__device__ __forceinline__ void cpasync16(uint32_t dst, const void* g) {
    asm volatile("cp.async.cg.shared.global [%0], [%1], 16;" :: "r"(dst), "l"(g));
}
#define CP_COMMIT() asm volatile("cp.async.commit_group;")
#define CP_WAIT(n)  asm volatile("cp.async.wait_group %0;" :: "n"(n))

#define LDMX4(R, addr) \
    asm volatile("ldmatrix.sync.aligned.m8n8.x4.shared.b16 {%0,%1,%2,%3}, [%4];" \
                 : "=r"((R)[0]), "=r"((R)[1]), "=r"((R)[2]), "=r"((R)[3]) : "r"(addr))

// fp8 MMA with f16 accumulator (2 packed regs)
__device__ __forceinline__ void mma16832h(uint32_t* c, const uint32_t* a, const uint32_t* b) {
    asm volatile(
        "mma.sync.aligned.m16n8k32.row.col.f16.e4m3.e4m3.f16 "
        "{%0,%1}, {%2,%3,%4,%5}, {%6,%7}, {%0,%1};"
        : "+r"(c[0]), "+r"(c[1])
        : "r"(a[0]), "r"(a[1]), "r"(a[2]), "r"(a[3]), "r"(b[0]), "r"(b[1]));
}

// packed 2^x for two halves — ONE MUFU op per two exponentials
__device__ __forceinline__ __half2 hexp2_x2(__half2 x) {
    __half2 r;
    asm("ex2.approx.f16x2 %0, %1;"
        : "=r"(*(uint32_t*)&r) : "r"(*(const uint32_t*)&x));
    return r;
}

__device__ __forceinline__ uint32_t pack4_e4m3(float v0, float v1, float v2, float v3) {
    uint16_t h01, h23;
    asm("cvt.rn.satfinite.e4m3x2.f32 %0, %1, %2;" : "=h"(h01) : "f"(v1), "f"(v0));
    asm("cvt.rn.satfinite.e4m3x2.f32 %0, %1, %2;" : "=h"(h23) : "f"(v3), "f"(v2));
    return (uint32_t)h01 | ((uint32_t)h23 << 16);
}

// SW64 swizzle for 64B-wide rows (conflict-free ldmatrix over 8 rows)
__device__ __forceinline__ uint32_t sw64(uint32_t off) {
    return off ^ ((off >> 3) & 0x30);
}

// -------------------------------------------------------------------------
// Kernel 1: warp-per-row-pair normalize (best measured: 9.3us, R10 exact).
// -------------------------------------------------------------------------
__global__ __launch_bounds__(128) void normalize_kernel(const float* __restrict__ z) {
    int warp = threadIdx.x >> 5, lane = threadIdx.x & 31;
    int row = blockIdx.x * 4 + warp;

    const float4* z1p = (const float4*)(z + (size_t)row * DIM);
    const float4* z2p = (const float4*)(z + (size_t)(row + NR) * DIM);

    float4 a[8];
    float s1 = 0.f, s2 = 0.f, s12 = 0.f;
    #pragma unroll
    for (int i = 0; i < 8; i++) {
        a[i] = z1p[lane + 32 * i];
        float4 b = z2p[lane + 32 * i];
        s1  += a[i].x * a[i].x + a[i].y * a[i].y + a[i].z * a[i].z + a[i].w * a[i].w;
        s2  += b.x * b.x + b.y * b.y + b.z * b.z + b.w * b.w;
        s12 += a[i].x * b.x + a[i].y * b.y + a[i].z * b.z + a[i].w * b.w;
    }
    #pragma unroll
    for (int o = 16; o; o >>= 1) {
        s1  += __shfl_xor_sync(0xFFFFFFFFu, s1, o);
        s2  += __shfl_xor_sync(0xFFFFFFFFu, s2, o);
        s12 += __shfl_xor_sync(0xFFFFFFFFu, s12, o);
    }
    float inv1 = 1.f / fmaxf(sqrtf(s1), 1e-12f);
    float inv2 = 1.f / fmaxf(sqrtf(s2), 1e-12f);
    float q1 = 16.f * inv1;

    uint32_t* dst = (uint32_t*)(g_zq + (size_t)row * DIM);
    #pragma unroll
    for (int i = 0; i < 8; i++) {
        dst[lane + 32 * i] = pack4_e4m3(a[i].x * q1, a[i].y * q1, a[i].z * q1, a[i].w * q1);
    }
    if (lane == 0) {
        float n1sq = s1 * inv1 * inv1;
        float n2sq = s2 * inv2 * inv2;
        float dp = n1sq + n2sq - 2.f * s12 * inv1 * inv2;
        g_pos[row] = logf(__expf(-0.5f * dp) + 1e-8f) + 1.f;
    }
}

// -------------------------------------------------------------------------
// Kernel 2: fp8 Gram (f16 acc) + f16x2 exp2 epilogue (R10 mainloop exact).
// Tile order: 496 off-diag tiles first, 32 light diag tiles LAST so the
// drain tail of the 1.78-wave launch is filled by short CTAs.
// 528 CTAs x 256 thr, 2 CTAs/SM. CTA tile 128x128; warp tile 64x32.
// 16 K-stages of 64B; 3-stage static-smem ring.
// -------------------------------------------------------------------------
__global__ __launch_bounds__(256, 2) void gram_kernel() {
    __shared__ uint8_t dsm[SMEM_TOTAL];
    uint32_t smem_base = su32(dsm);
    int tid = threadIdx.x;
    int warp = tid >> 5, lane = tid & 31;
    int wr = warp >> 2, wc = warp & 3;   // warp grid 2 x 4 (rows x cols)

    // bid -> (ti, tj): off-diag (ti<tj) for bid<NOFF, diag for bid>=NOFF
    int ti, tj;
    if (blockIdx.x < NOFF) {
        int t = 0, rem = blockIdx.x;
        #pragma unroll 1
        while (rem >= NT - 1 - t) { rem -= NT - 1 - t; t++; }
        ti = t; tj = t + 1 + rem;
    } else {
        ti = tj = blockIdx.x - NOFF;
    }

    bool diag = (ti == tj);
    bool active = !(diag && (wc * 32 + 32 <= wr * 64));

    const uint8_t* Abase = g_zq + (size_t)ti * 128 * DIM;
    const uint8_t* Bbase = g_zq + (size_t)tj * 128 * DIM;

    uint32_t acc[4][4][2];   // f16x2 accumulators (= 256 * dot pairs)
    #pragma unroll
    for (int i = 0; i < 4; i++)
        #pragma unroll
        for (int j = 0; j < 4; j++) { acc[i][j][0] = 0u; acc[i][j][1] = 0u; }

    #define LOAD_STAGE(s, slot)                                                   \
        do {                                                                      \
            uint32_t base_ = smem_base + (slot) * STAGE_BYTES;                    \
            const uint8_t* Ak = Abase + (s) * BKB;                                \
            const uint8_t* Bk = Bbase + (s) * BKB;                                \
            _Pragma("unroll")                                                     \
            for (int x = tid; x < 512; x += 256) {                                \
                int r_ = x >> 2, c_ = x & 3;                                      \
                uint32_t off = sw64((uint32_t)(r_ * 64 + c_ * 16));               \
                cpasync16(base_ + off, Ak + (size_t)r_ * DIM + c_ * 16);          \
            }                                                                     \
            _Pragma("unroll")                                                     \
            for (int x = tid; x < 512; x += 256) {                                \
                int r_ = x >> 2, c_ = x & 3;                                      \
                uint32_t off = sw64((uint32_t)(r_ * 64 + c_ * 16));               \
                cpasync16(base_ + 8192 + off, Bk + (size_t)r_ * DIM + c_ * 16);   \
            }                                                                     \
            CP_COMMIT();                                                          \
        } while (0)

    LOAD_STAGE(0, 0);
    LOAD_STAGE(1, 1);
    LOAD_STAGE(2, 2);

    int slot = 0;
    #pragma unroll 1
    for (int s = 0; s < NSTG; s++) {
        if (s <= NSTG - 3)      CP_WAIT(2);
        else if (s == NSTG - 2) CP_WAIT(1);
        else                    CP_WAIT(0);
        __syncthreads();

        if (active) {
            uint32_t sa = smem_base + slot * STAGE_BYTES;
            uint32_t sb = sa + 8192;
            #pragma unroll
            for (int kk = 0; kk < 2; kk++) {
                uint32_t af[4][4];
                #pragma unroll
                for (int mi = 0; mi < 4; mi++) {
                    int r = wr * 64 + mi * 16 + (lane & 7) + ((lane >> 3) & 1) * 8;
                    int cb = kk * 32 + ((lane >> 4) & 1) * 16;
                    LDMX4(af[mi], sa + sw64((uint32_t)(r * 64 + cb)));
                }
                uint32_t bf[4][2];
                #pragma unroll
                for (int p = 0; p < 2; p++) {
                    int r = wc * 32 + p * 16 + ((lane >> 4) & 1) * 8 + (lane & 7);
                    int cb = kk * 32 + ((lane >> 3) & 1) * 16;
                    uint32_t t[4];
                    LDMX4(t, sb + sw64((uint32_t)(r * 64 + cb)));
                    bf[2 * p + 0][0] = t[0]; bf[2 * p + 0][1] = t[1];
                    bf[2 * p + 1][0] = t[2]; bf[2 * p + 1][1] = t[3];
                }
                #pragma unroll
                for (int mi = 0; mi < 4; mi++)
                    #pragma unroll
                    for (int ni = 0; ni < 4; ni++)
                        mma16832h(acc[mi][ni], af[mi], bf[ni]);
            }
        }

        if (s + 3 < NSTG) {
            __syncthreads();
            LOAD_STAGE(s + 3, slot);
        }
        slot = (slot == 2) ? 0 : slot + 1;
    }

    // ---- f16x2 epilogue: rows unit-norm -> g = exp(dot-1) = 2^(acc*k - log2e)
    const __half2 k2 = __float2half2_rn(1.44269504f / 256.f);
    const __half2 c2 = __float2half2_rn(-1.44269504f);
    __half2 hs0 = __float2half2_rn(0.f), hs1 = hs0, hs2 = hs0, hs3 = hs0;

    float local = 0.f;
    if (active) {
        if (!diag) {
            #pragma unroll
            for (int mi = 0; mi < 4; mi++)
                #pragma unroll
                for (int ni = 0; ni < 4; ni++) {
                    __half2 g0 = hexp2_x2(__hfma2(*(__half2*)&acc[mi][ni][0], k2, c2));
                    __half2 g1 = hexp2_x2(__hfma2(*(__half2*)&acc[mi][ni][1], k2, c2));
                    if (ni & 1) { hs1 = __hadd2(hs1, g0); hs3 = __hadd2(hs3, g1); }
                    else        { hs0 = __hadd2(hs0, g0); hs2 = __hadd2(hs2, g1); }
                }
        } else {
            int r0 = lane >> 2, c0 = (lane & 3) * 2;
            #pragma unroll
            for (int mi = 0; mi < 4; mi++) {
                int gi0 = wr * 64 + mi * 16 + r0;
                #pragma unroll
                for (int ni = 0; ni < 4; ni++) {
                    int gj0 = wc * 32 + ni * 8 + c0;
                    __half2 m0 = __floats2half2_rn(gj0 > gi0 ? 1.f : 0.f,
                                                   gj0 + 1 > gi0 ? 1.f : 0.f);
                    __half2 m1 = __floats2half2_rn(gj0 > gi0 + 8 ? 1.f : 0.f,
                                                   gj0 + 1 > gi0 + 8 ? 1.f : 0.f);
                    __half2 g0 = hexp2_x2(__hfma2(*(__half2*)&acc[mi][ni][0], k2, c2));
                    __half2 g1 = hexp2_x2(__hfma2(*(__half2*)&acc[mi][ni][1], k2, c2));
                    hs0 = __hfma2(g0, m0, hs0);
                    hs2 = __hfma2(g1, m1, hs2);
                }
            }
        }
        __half2 hs = __hadd2(__hadd2(hs0, hs1), __hadd2(hs2, hs3));
        local = 2.f * (__low2float(hs) + __high2float(hs));
    }

    #pragma unroll
    for (int o = 16; o; o >>= 1) local += __shfl_xor_sync(0xFFFFFFFFu, local, o);
    __shared__ float part[8];
    if (lane == 0) part[warp] = local;
    __syncthreads();
    if (tid == 0) {
        float tot = 0.f;
        #pragma unroll
        for (int i = 0; i < 8; i++) tot += part[i];
        g_negpart[blockIdx.x] = tot;
    }
}

// -------------------------------------------------------------------------
// Kernel 3: deterministic finalize (single-pass loads, then two reductions)
// -------------------------------------------------------------------------
__global__ __launch_bounds__(256) void finalize_kernel(float* out) {
    __shared__ double shp[256];
    __shared__ double shn[256];
    int tid = threadIdx.x;

    double p = 0.0, n = 0.0;
    for (int i = tid; i < NR; i += 256) p += (double)g_pos[i];
    for (int i = tid; i < NBLK; i += 256) n += (double)g_negpart[i];
    shp[tid] = p;
    shn[tid] = n;
    __syncthreads();
    for (int s = 128; s; s >>= 1) {
        if (tid < s) { shp[tid] += shp[tid + s]; shn[tid] += shn[tid + s]; }
        __syncthreads();
    }
    if (tid == 0) {
        double star_mean = shn[0] / ((double)NR * (double)(NR - 1)) + 1e-8;
        double loss = -(shp[0] / (double)NR) + 64.0 * star_mean;
        out[0] = (float)loss;
    }
}

extern "C" void kernel_launch(void* const* d_in, const int* in_sizes, int n_in,
                              void* d_out, int out_size) {
    const float* z = (const float*)d_in[0];
    float* out = (float*)d_out;
    normalize_kernel<<<1024, 128>>>(z);
    gram_kernel<<<NBLK, 256>>>();
    finalize_kernel<<<1, 256>>>(out);
}